// round 17
// baseline (speedup 1.0000x reference)
#include <cuda_runtime.h>
#include <cstdint>

// Problem dims (fixed)
#define B_  16
#define U_  64
#define T_  128
#define E_  128
#define HID_ 256
#define H_  4
#define ENC_H_ 128
#define IN_DIM_ 32

typedef unsigned long long ull;

// Scratch (device globals: no allocation allowed)
__device__ float g_qu[B_ * U_ * HID_];    // ue @ fw1[:E]          (1024 x 256)
__device__ float g_kh[B_ * T_ * HID_];    // te @ fw1[E:]          (2048 x 256)
__device__ float g_qb[H_ * HID_];         // head_q @ fw1[:E] + fb1 (4 x 256)
__device__ float g_part[2][B_ * H_ * U_ * T_];  // d-half partial sums

// k-pair packed weights: Wp[k2][c] = (W[2k2][c], W[2k2+1][c]) as float2
#define UW0_OFF 0
#define UW1_OFF 4096
#define UW2_OFF 20480
#define TW0_OFF 36864
#define TW1_OFF 40960
#define TW2_OFF 57344
#define FW1_OFF 73728
#define WPACK_TOTAL 139264
__device__ float g_wpack[WPACK_TOTAL];

// ---- packed f32x2 helpers (Blackwell) ----
__device__ __forceinline__ ull add2(ull a, ull b) {
    ull r;
    asm("add.rn.f32x2 %0, %1, %2;" : "=l"(r) : "l"(a), "l"(b));
    return r;
}
__device__ __forceinline__ void fma2(ull& acc, ull a, ull b) {
    asm("fma.rn.f32x2 %0, %1, %2, %0;" : "+l"(acc) : "l"(a), "l"(b));
}
__device__ __forceinline__ ull relu2(ull x) {
    float lo, hi;
    asm("mov.b64 {%0,%1}, %2;" : "=f"(lo), "=f"(hi) : "l"(x));
    lo = fmaxf(lo, 0.f);
    hi = fmaxf(hi, 0.f);
    ull r;
    asm("mov.b64 %0, {%1,%2};" : "=l"(r) : "f"(lo), "f"(hi));
    return r;
}
__device__ __forceinline__ float hsum2(ull x) {
    float lo, hi;
    asm("mov.b64 {%0,%1}, %2;" : "=f"(lo), "=f"(hi) : "l"(x));
    return lo + hi;
}

// ---------------------------------------------------------------------------
// Pack kernel: interleave k-pairs of every weight matrix (proven in R11).
// Segment table (blocks of 256 pairs):
//  [0,8) uw0 | [8,40) uw1 | [40,72) uw2 | [72,80) tw0 | [80,112) tw1
//  [112,144) tw2 | [144,272) fw1
// ---------------------------------------------------------------------------
__global__ __launch_bounds__(256) void pack_kernel(
    const float* __restrict__ uw0, const float* __restrict__ uw1,
    const float* __restrict__ uw2, const float* __restrict__ tw0,
    const float* __restrict__ tw1, const float* __restrict__ tw2,
    const float* __restrict__ fw1)
{
    const int b = blockIdx.x;
    const int t = threadIdx.x;
    const float* src;
    int C, dstoff, pair0;
    if      (b < 8)   { src = uw0; C = 128; dstoff = UW0_OFF; pair0 = b * 256; }
    else if (b < 40)  { src = uw1; C = 128; dstoff = UW1_OFF; pair0 = (b - 8) * 256; }
    else if (b < 72)  { src = uw2; C = 128; dstoff = UW2_OFF; pair0 = (b - 40) * 256; }
    else if (b < 80)  { src = tw0; C = 128; dstoff = TW0_OFF; pair0 = (b - 72) * 256; }
    else if (b < 112) { src = tw1; C = 128; dstoff = TW1_OFF; pair0 = (b - 80) * 256; }
    else if (b < 144) { src = tw2; C = 128; dstoff = TW2_OFF; pair0 = (b - 112) * 256; }
    else              { src = fw1; C = 256; dstoff = FW1_OFF; pair0 = (b - 144) * 256; }

    int p = pair0 + t;
    int k2 = (C == 128) ? (p >> 7) : (p >> 8);
    int c  = (C == 128) ? (p & 127) : (p & 255);
    float lo = src[(2 * k2) * C + c];
    float hi = src[(2 * k2 + 1) * C + c];
    *(float2*)&g_wpack[dstoff + (size_t)p * 2] = make_float2(lo, hi);
}

// ---------------------------------------------------------------------------
// Packed weight load: 4 k-pairs (8 k) for one col.  LDG.64, coalesced.
// p = &wpack[(k2*C + j)*2], C2 = C*2 floats per k2 row.
// ---------------------------------------------------------------------------
__device__ __forceinline__ void ldwp4(ull w[4], const float* __restrict__ p, int C2)
{
    w[0] = __ldg((const ull*)(p));
    w[1] = __ldg((const ull*)(p + C2));
    w[2] = __ldg((const ull*)(p + 2 * C2));
    w[3] = __ldg((const ull*)(p + 3 * C2));
}

// FMA block: 4 rows x 1 col x 8 k with packed weights. 16 fma2.
__device__ __forceinline__ void fma8p(
    ull acc[4], const ull w[4],
    const float* a0, const float* a1, const float* a2, const float* a3)
{
    ulonglong2 x0a = *(const ulonglong2*)a0, x0b = *(const ulonglong2*)(a0 + 4);
    ulonglong2 x1a = *(const ulonglong2*)a1, x1b = *(const ulonglong2*)(a1 + 4);
    ulonglong2 x2a = *(const ulonglong2*)a2, x2b = *(const ulonglong2*)(a2 + 4);
    ulonglong2 x3a = *(const ulonglong2*)a3, x3b = *(const ulonglong2*)(a3 + 4);
    fma2(acc[0], x0a.x, w[0]); fma2(acc[0], x0a.y, w[1]);
    fma2(acc[0], x0b.x, w[2]); fma2(acc[0], x0b.y, w[3]);
    fma2(acc[1], x1a.x, w[0]); fma2(acc[1], x1a.y, w[1]);
    fma2(acc[1], x1b.x, w[2]); fma2(acc[1], x1b.y, w[3]);
    fma2(acc[2], x2a.x, w[0]); fma2(acc[2], x2a.y, w[1]);
    fma2(acc[2], x2b.x, w[2]); fma2(acc[2], x2b.y, w[3]);
    fma2(acc[3], x3a.x, w[0]); fma2(acc[3], x3a.y, w[1]);
    fma2(acc[3], x3b.x, w[2]); fma2(acc[3], x3b.y, w[3]);
}

// Layer with one-iteration weight prefetch (software pipeline).
// wcolp = &wpack[j*2] of the layer's packed matrix, C = cols, K = k depth.
__device__ __forceinline__ void pipelayerp(
    ull acc[4], const float* __restrict__ wcolp, int C, int K,
    const float* act, int astr, int rb)
{
    const int C2 = C * 2;
    ull wbuf[4], wn[4];
    ldwp4(wbuf, wcolp, C2);
    #pragma unroll
    for (int k = 0; k < 128; k += 8) {       // upper bound; guarded by K
        if (k >= K) break;
        if (k + 8 < K) ldwp4(wn, wcolp + (size_t)(k + 8) / 2 * C2, C2);
        fma8p(acc, wbuf,
              act + (rb + 0) * astr + k, act + (rb + 1) * astr + k,
              act + (rb + 2) * astr + k, act + (rb + 3) * astr + k);
        #pragma unroll
        for (int q = 0; q < 4; ++q) wbuf[q] = wn[q];
    }
}

// ---------------------------------------------------------------------------
// Fused encoder: blocks [0,128) = UAV (8 rows), [128,384) = task, 384 = qb.
// 256 threads: j = tid&127 owns col j, rb = (tid>>7)*4 owns 4 of the 8 rows.
// Weights: packed k-pairs, LDG.64 coalesced, 1-iter prefetch.
// Acts: broadcast LDS.128 from row-major smem.
// ---------------------------------------------------------------------------
__global__ __launch_bounds__(256) void enc_fused_kernel(
    const float* __restrict__ uav_feat, const float* __restrict__ task_feat,
    const float* __restrict__ ub0, const float* __restrict__ ub1,
    const float* __restrict__ ub2, const float* __restrict__ tb0,
    const float* __restrict__ tb1, const float* __restrict__ tb2,
    const float* __restrict__ head_q, const float* __restrict__ fw1,
    const float* __restrict__ fb1)
{
    const int bx = blockIdx.x;
    const int tid = threadIdx.x;

    // ---------------- qb block ----------------
    if (bx == 384) {
        int d = tid;   // 0..255
        #pragma unroll
        for (int h = 0; h < H_; ++h) {
            float acc = fb1[d];
            #pragma unroll 8
            for (int k = 0; k < E_; ++k)
                acc += head_q[h * E_ + k] * fw1[k * HID_ + d];
            g_qb[h * HID_ + d] = acc;
        }
        return;
    }

    const int is_task = (bx >= 128);
    const float* x   = is_task ? task_feat : uav_feat;
    const float* wp0 = g_wpack + (is_task ? TW0_OFF : UW0_OFF);
    const float* wp1 = g_wpack + (is_task ? TW1_OFF : UW1_OFF);
    const float* wp2 = g_wpack + (is_task ? TW2_OFF : UW2_OFF);
    const float* wpf = g_wpack + FW1_OFF + (is_task ? (size_t)E_ * HID_ : 0);
    const float* b0  = is_task ? tb0 : ub0;
    const float* b1  = is_task ? tb1 : ub1;
    const float* b2  = is_task ? tb2 : ub2;
    float* out       = is_task ? g_kh : g_qu;
    const int row0   = (is_task ? (bx - 128) : bx) * 8;

    __shared__ float xs[8][IN_DIM_];
    __shared__ float bufA[8][ENC_H_];
    __shared__ float bufB[8][ENC_H_];

    // load 8x32 input tile (256 threads exactly)
    xs[tid >> 5][tid & 31] = x[(size_t)(row0 + (tid >> 5)) * IN_DIM_ + (tid & 31)];
    __syncthreads();

    const int j  = tid & 127;
    const int rb = (tid >> 7) * 4;    // rows rb..rb+3 (warp-uniform)
    ull acc[4];

    // ---- layer 0: 32 -> 128, relu ----
    acc[0] = acc[1] = acc[2] = acc[3] = 0ULL;
    pipelayerp(acc, wp0 + j * 2, ENC_H_, IN_DIM_, &xs[0][0], IN_DIM_, rb);
    {
        float bv = b0[j];
        #pragma unroll
        for (int r = 0; r < 4; ++r)
            bufA[rb + r][j] = fmaxf(hsum2(acc[r]) + bv, 0.f);
    }
    __syncthreads();

    // ---- layer 1: 128 -> 128, relu ----
    acc[0] = acc[1] = acc[2] = acc[3] = 0ULL;
    pipelayerp(acc, wp1 + j * 2, ENC_H_, ENC_H_, &bufA[0][0], ENC_H_, rb);
    {
        float bv = b1[j];
        #pragma unroll
        for (int r = 0; r < 4; ++r)
            bufB[rb + r][j] = fmaxf(hsum2(acc[r]) + bv, 0.f);
    }
    __syncthreads();

    // ---- layer 2: 128 -> 128 (no relu) ----
    acc[0] = acc[1] = acc[2] = acc[3] = 0ULL;
    pipelayerp(acc, wp2 + j * 2, ENC_H_, ENC_H_, &bufB[0][0], ENC_H_, rb);
    __syncthreads();   // bufA reads done
    {
        float bv = b2[j];
        #pragma unroll
        for (int r = 0; r < 4; ++r)
            bufA[rb + r][j] = hsum2(acc[r]) + bv;
    }
    __syncthreads();

    // ---- projection through fw1 slice: 128 -> 256 (2 col passes) ----
    #pragma unroll
    for (int p = 0; p < 2; ++p) {
        int col = j + p * 128;
        acc[0] = acc[1] = acc[2] = acc[3] = 0ULL;
        pipelayerp(acc, wpf + col * 2, HID_, E_, &bufA[0][0], ENC_H_, rb);
        #pragma unroll
        for (int r = 0; r < 4; ++r)
            out[(size_t)(row0 + rb + r) * HID_ + col] = hsum2(acc[r]);
    }
}

// ---------------------------------------------------------------------------
// Stage E (t-split x d-half): partial[dh][z][u][t] =
//   sum_{d in half} relu(qu[b,u,d]+qb[h,d]+kh[b,t,d]) * fw2[d]
// Grid (tblk:2, dh:2, z:64) = 256 blocks, 512 threads, thread tile 4u x 2t.
// ---------------------------------------------------------------------------
#define DH 128
#define ESTR 132
#define SMEM_E_FLOATS (64 * ESTR + 64 * ESTR + DH)
#define SMEM_E_BYTES  (SMEM_E_FLOATS * 4)

__global__ __launch_bounds__(512, 2) void stageE_k(
    const float* __restrict__ fw2)
{
    extern __shared__ float smem[];
    float* qs   = smem;                        // [64][132]
    float* ks   = smem + 64 * ESTR;            // [64][132]
    float* fw2s = ks + 64 * ESTR;              // [128]

    const int tid = threadIdx.x;
    const int t0  = blockIdx.x * 64;           // 0 or 64
    const int dh  = blockIdx.y;                // 0..1
    const int z   = blockIdx.z;                // b*H + h
    const int b   = z >> 2;
    const int h   = z & 3;
    const int d0  = dh * DH;

    if (tid < DH / 4)
        ((float4*)fw2s)[tid] = ((const float4*)(fw2 + d0))[tid];

    {
        const float4* qb4 = (const float4*)(g_qb + h * HID_ + d0);
        #pragma unroll
        for (int p = 0; p < 4; ++p) {
            int idx = tid + p * 512;
            int u   = idx >> 5;
            int d4  = idx & 31;
            float4 a = ((const float4*)(g_qu + (size_t)(b * U_ + u) * HID_ + d0))[d4];
            float4 qb = qb4[d4];
            a.x += qb.x; a.y += qb.y; a.z += qb.z; a.w += qb.w;
            ((float4*)(qs + u * ESTR))[d4] = a;
        }
    }
    {
        #pragma unroll
        for (int p = 0; p < 4; ++p) {
            int idx = tid + p * 512;
            int t   = idx >> 5;
            int d4  = idx & 31;
            ((float4*)(ks + t * ESTR))[d4] =
                ((const float4*)(g_kh + (size_t)(b * T_ + t0 + t) * HID_ + d0))[d4];
        }
    }
    __syncthreads();

    const int tg = tid & 31;       // t = t0 + tg + 32*jj (jj 0..1)
    const int ug = tid >> 5;       // u = ug*4 + i (warp-uniform)

    ull acc[4][2];
    #pragma unroll
    for (int i = 0; i < 4; ++i) { acc[i][0] = 0ULL; acc[i][1] = 0ULL; }

    const float* qbase = qs + (ug * 4) * ESTR;
    const float* kbase = ks + tg * ESTR;

    #pragma unroll 4
    for (int d4 = 0; d4 < DH / 4; ++d4) {
        ulonglong2 wv = *(const ulonglong2*)(fw2s + d4 * 4);
        ulonglong2 qv[4], kv[2];
        #pragma unroll
        for (int i = 0; i < 4; ++i)
            qv[i] = *(const ulonglong2*)(qbase + i * ESTR + d4 * 4);
        #pragma unroll
        for (int jj = 0; jj < 2; ++jj)
            kv[jj] = *(const ulonglong2*)(kbase + jj * 32 * ESTR + d4 * 4);

        #pragma unroll
        for (int i = 0; i < 4; ++i) {
            #pragma unroll
            for (int jj = 0; jj < 2; ++jj) {
                fma2(acc[i][jj], relu2(add2(qv[i].x, kv[jj].x)), wv.x);
                fma2(acc[i][jj], relu2(add2(qv[i].y, kv[jj].y)), wv.y);
            }
        }
    }

    float* part = g_part[dh] + (size_t)z * U_ * T_;
    #pragma unroll
    for (int i = 0; i < 4; ++i) {
        float* row = part + (ug * 4 + i) * T_ + t0 + tg;
        row[0]  = hsum2(acc[i][0]);
        row[32] = hsum2(acc[i][1]);
    }
}

// ---------------------------------------------------------------------------
// Combine: out = part0 + part1 + fb2 (1 float4 per thread, 512 blocks)
// ---------------------------------------------------------------------------
__global__ __launch_bounds__(256) void combine_kernel(
    float* __restrict__ out, const float* __restrict__ fb2)
{
    const float bias = fb2[0];
    int i = blockIdx.x * 256 + threadIdx.x;      // float4 index, 131072 total
    float4 a = ((const float4*)g_part[0])[i];
    float4 b = ((const float4*)g_part[1])[i];
    float4 r;
    r.x = a.x + b.x + bias;
    r.y = a.y + b.y + bias;
    r.z = a.z + b.z + bias;
    r.w = a.w + b.w + bias;
    ((float4*)out)[i] = r;
}

// ---------------------------------------------------------------------------
extern "C" void kernel_launch(void* const* d_in, const int* in_sizes, int n_in,
                              void* d_out, int out_size)
{
    const float* uav_feat = (const float*)d_in[0];
    const float* task_feat = (const float*)d_in[1];
    const float* uw0 = (const float*)d_in[2];
    const float* ub0 = (const float*)d_in[3];
    const float* uw1 = (const float*)d_in[4];
    const float* ub1 = (const float*)d_in[5];
    const float* uw2 = (const float*)d_in[6];
    const float* ub2 = (const float*)d_in[7];
    const float* tw0 = (const float*)d_in[8];
    const float* tb0 = (const float*)d_in[9];
    const float* tw1 = (const float*)d_in[10];
    const float* tb1 = (const float*)d_in[11];
    const float* tw2 = (const float*)d_in[12];
    const float* tb2 = (const float*)d_in[13];
    const float* head_q = (const float*)d_in[14];
    const float* fw1 = (const float*)d_in[15];
    const float* fb1 = (const float*)d_in[16];
    const float* fw2 = (const float*)d_in[17];
    const float* fb2 = (const float*)d_in[18];
    float* out = (float*)d_out;

    cudaFuncSetAttribute(stageE_k,
                         cudaFuncAttributeMaxDynamicSharedMemorySize,
                         SMEM_E_BYTES);

    // 1) pack weights into k-pair layout
    pack_kernel<<<272, 256>>>(uw0, uw1, uw2, tw0, tw1, tw2, fw1);

    // 2) encoders + qb (385 blocks x 256 threads, 8 rows/block)
    enc_fused_kernel<<<385, 256>>>(uav_feat, task_feat,
                                   ub0, ub1, ub2, tb0, tb1, tb2,
                                   head_q, fw1, fb1);

    // 3) Stage E over (t:2, d-half:2, z:64)
    dim3 grid(2, 2, B_ * H_);
    stageE_k<<<grid, 512, SMEM_E_BYTES>>>(fw2);

    // 4) combine partials + bias
    combine_kernel<<<512, 256>>>(out, fb2);
}